// round 4
// baseline (speedup 1.0000x reference)
#include <cuda_runtime.h>

#define POOL 7
#define CELLS (POOL * POOL)

// One block per box, 256 threads. tid&63 = channel-quad, tid>>6 = cell group
// (0..3). Group g handles cells g, g+4, g+8, ... processed in PAIRS
// (c, c+4) with interleaved loads: 8 LDG.128 in flight per lane while the
// first cell's lerp+store executes under the second cell's load shadow.

__device__ __forceinline__ float4 lerp4(float4 tl, float4 tr, float4 bl, float4 br,
                                        float fx, float fy)
{
    float4 r;
    float tx = tl.x + (tr.x - tl.x) * fx;
    float ty = tl.y + (tr.y - tl.y) * fx;
    float tz = tl.z + (tr.z - tl.z) * fx;
    float tw = tl.w + (tr.w - tl.w) * fx;
    float bx = bl.x + (br.x - bl.x) * fx;
    float by = bl.y + (br.y - bl.y) * fx;
    float bz = bl.z + (br.z - bl.z) * fx;
    float bw = bl.w + (br.w - bl.w) * fx;
    r.x = tx + (bx - tx) * fy;
    r.y = ty + (by - ty) * fy;
    r.z = tz + (bz - tz) * fy;
    r.w = tw + (bw - tw) * fy;
    return r;
}

__global__ __launch_bounds__(256) void roialign_c256_kernel(
    const float* __restrict__ boxes,
    const float* __restrict__ meta,
    const float* __restrict__ f2,
    const float* __restrict__ f3,
    const float* __restrict__ f4,
    const float* __restrict__ f5,
    float* __restrict__ out,
    int N)
{
    __shared__ int4   s_off[CELLS];          // quad offsets: tl,tr,bl,br
    __shared__ float2 s_f[CELLS];            // fx, fy
    __shared__ const float4* s_base;

    const int bn  = blockIdx.x;
    const int tid = threadIdx.x;
    const int C   = 256;

    if (tid < CELLS) {
        const int b = bn / N;
        const float* bx = boxes + (size_t)bn * 4;
        float y1 = bx[0], x1 = bx[1], y2 = bx[2], x2 = bx[3];
        float h = y2 - y1, w = x2 - x1;

        float scale = 224.0f / sqrtf(meta[4] * meta[5]);
        float lvl = log2f(sqrtf(h * w) / scale);
        float rl  = 4.0f + rintf(lvl);                 // half-to-even
        rl = fminf(fmaxf(rl, 2.0f), 5.0f);
        int li = (int)rl - 2;
        int H  = 256 >> li;

        const float* fm = (li == 0) ? f2 : (li == 1) ? f3 : (li == 2) ? f4 : f5;
        const float* base = fm + (size_t)b * H * H * C;

        int py = tid / POOL;
        int px = tid - py * POOL;

        float Hm1 = (float)(H - 1);
        float ys = y1 * Hm1 + (float)py * ((h * Hm1) / 6.0f);
        float xs = x1 * Hm1 + (float)px * ((w * Hm1) / 6.0f);

        float y0f = floorf(ys), x0f = floorf(xs);
        int y0  = min(max((int)y0f, 0), H - 1);
        int x0  = min(max((int)x0f, 0), H - 1);
        int y1i = min(y0 + 1, H - 1);
        int x1i = min(x0 + 1, H - 1);

        int c4 = C >> 2;   // 64 quads per pixel row
        int4 off;
        off.x = (y0  * H + x0 ) * c4;
        off.y = (y0  * H + x1i) * c4;
        off.z = (y1i * H + x0 ) * c4;
        off.w = (y1i * H + x1i) * c4;
        s_off[tid] = off;
        s_f[tid] = make_float2(xs - x0f, ys - y0f);
        if (tid == 0) s_base = (const float4*)base;
    }
    __syncthreads();

    const float4* base = s_base;
    const int c4  = tid & 63;        // channel-quad
    const int grp = tid >> 6;        // 0..3

    float4* ob = (float4*)out + (size_t)bn * CELLS * 64;

    int c = grp;
    // paired, software-pipelined iterations
    for (; c + 4 < CELLS; c += 8) {
        int4   offA = s_off[c];
        float2 fA   = s_f[c];
        int4   offB = s_off[c + 4];
        float2 fB   = s_f[c + 4];

        // front-batch 8 independent loads
        float4 tlA = __ldg(base + offA.x + c4);
        float4 trA = __ldg(base + offA.y + c4);
        float4 blA = __ldg(base + offA.z + c4);
        float4 brA = __ldg(base + offA.w + c4);
        float4 tlB = __ldg(base + offB.x + c4);
        float4 trB = __ldg(base + offB.y + c4);
        float4 blB = __ldg(base + offB.z + c4);
        float4 brB = __ldg(base + offB.w + c4);

        // compute+store A under B's load shadow
        __stcs(ob + c * 64 + c4,       lerp4(tlA, trA, blA, brA, fA.x, fA.y));
        __stcs(ob + (c + 4) * 64 + c4, lerp4(tlB, trB, blB, brB, fB.x, fB.y));
    }
    // tail (at most one cell per group)
    if (c < CELLS) {
        int4   off = s_off[c];
        float2 f   = s_f[c];
        float4 tl = __ldg(base + off.x + c4);
        float4 tr = __ldg(base + off.y + c4);
        float4 bl = __ldg(base + off.z + c4);
        float4 br = __ldg(base + off.w + c4);
        __stcs(ob + c * 64 + c4, lerp4(tl, tr, bl, br, f.x, f.y));
    }
}

// ---------------- generic fallback (any C divisible by 4) ----------------

struct __align__(16) CellParam {
    const float4* tl;
    const float4* tr;
    const float4* bl;
    const float4* br;
    float fx, fy;
    float pad0, pad1;
};

__global__ __launch_bounds__(256) void roialign_generic_kernel(
    const float* __restrict__ boxes,
    const float* __restrict__ meta,
    const float* __restrict__ f2,
    const float* __restrict__ f3,
    const float* __restrict__ f4,
    const float* __restrict__ f5,
    float* __restrict__ out,
    int N, int C)
{
    __shared__ CellParam cp[CELLS];
    const int bn  = blockIdx.x;
    const int tid = threadIdx.x;

    if (tid < CELLS) {
        const int b = bn / N;
        const float* bx = boxes + (size_t)bn * 4;
        float y1 = bx[0], x1 = bx[1], y2 = bx[2], x2 = bx[3];
        float h = y2 - y1, w = x2 - x1;
        float scale = 224.0f / sqrtf(meta[4] * meta[5]);
        float lvl = log2f(sqrtf(h * w) / scale);
        float rl  = 4.0f + rintf(lvl);
        rl = fminf(fmaxf(rl, 2.0f), 5.0f);
        int li = (int)rl - 2;
        int H  = 256 >> li;
        const float* fm = (li == 0) ? f2 : (li == 1) ? f3 : (li == 2) ? f4 : f5;
        const float* base = fm + (size_t)b * H * H * C;
        int py = tid / POOL;
        int px = tid - py * POOL;
        float Hm1 = (float)(H - 1);
        float ys = y1 * Hm1 + (float)py * ((h * Hm1) / 6.0f);
        float xs = x1 * Hm1 + (float)px * ((w * Hm1) / 6.0f);
        float y0f = floorf(ys), x0f = floorf(xs);
        int y0  = min(max((int)y0f, 0), H - 1);
        int x0  = min(max((int)x0f, 0), H - 1);
        int y1i = min(y0 + 1, H - 1);
        int x1i = min(x0 + 1, H - 1);
        CellParam p;
        p.tl = (const float4*)(base + (size_t)(y0  * H + x0 ) * C);
        p.tr = (const float4*)(base + (size_t)(y0  * H + x1i) * C);
        p.bl = (const float4*)(base + (size_t)(y1i * H + x0 ) * C);
        p.br = (const float4*)(base + (size_t)(y1i * H + x1i) * C);
        p.fx = xs - x0f;
        p.fy = ys - y0f;
        p.pad0 = 0.f; p.pad1 = 0.f;
        cp[tid] = p;
    }
    __syncthreads();

    const int c4pc = C >> 2;
    const int c4   = tid % c4pc;
    const int cw   = tid / c4pc;
    const int cstr = blockDim.x / c4pc;
    float4* ob = (float4*)out + (size_t)bn * CELLS * c4pc;

    for (int cell = cw; cell < CELLS; cell += cstr) {
        float fx = cp[cell].fx, fy = cp[cell].fy;
        float4 tl = __ldg(cp[cell].tl + c4);
        float4 tr = __ldg(cp[cell].tr + c4);
        float4 bl = __ldg(cp[cell].bl + c4);
        float4 br = __ldg(cp[cell].br + c4);
        ob[cell * c4pc + c4] = lerp4(tl, tr, bl, br, fx, fy);
    }
}

extern "C" void kernel_launch(void* const* d_in, const int* in_sizes, int n_in,
                              void* d_out, int out_size) {
    const float* boxes = (const float*)d_in[0];
    const float* meta  = (const float*)d_in[1];
    const float* f2    = (const float*)d_in[2];
    const float* f3    = (const float*)d_in[3];
    const float* f4    = (const float*)d_in[4];
    const float* f5    = (const float*)d_in[5];
    float* out = (float*)d_out;

    int B = in_sizes[1] / 14;
    int N = in_sizes[0] / (4 * B);
    int C = in_sizes[2] / (B * 256 * 256);

    int blocks = B * N;
    if (C == 256) {
        roialign_c256_kernel<<<blocks, 256>>>(boxes, meta, f2, f3, f4, f5, out, N);
    } else {
        roialign_generic_kernel<<<blocks, 256>>>(boxes, meta, f2, f3, f4, f5, out, N, C);
    }
}